// round 3
// baseline (speedup 1.0000x reference)
#include <cuda_runtime.h>
#include <cuda_bf16.h>
#include <stdint.h>

#define NN 50000
#define DIMK 64
#define BN_EPS 1e-5f
#define L2_EPS 1e-12f

// ---- scratch (device globals; no allocation allowed) ----
__device__ __align__(16) float g_h[NN * DIMK];     // h = x @ W
__device__ __align__(16) float g_acc[NN * DIMK];   // accumulator (self-loop + edges)
__device__ float g_deg[NN];
__device__ float g_dinv[NN];
__device__ float g_sum[DIMK];
__device__ float g_sumsq[DIMK];
__device__ int   g_is32;                           // 1 if edge_index is int32

// ---- 0) probe edge_index dtype: int64 high words are all 0 for values in [0,N) ----
__global__ void k_probe(const unsigned int* __restrict__ ei32) {
    int tid = threadIdx.x;
    unsigned int acc = 0;
    for (int i = tid; i < 2048; i += 256)
        acc |= ei32[2 * i + 1];
    __shared__ unsigned int sh[256];
    sh[tid] = acc;
    __syncthreads();
    for (int s = 128; s > 0; s >>= 1) {
        if (tid < s) sh[tid] |= sh[tid + s];
        __syncthreads();
    }
    if (tid == 0) g_is32 = (sh[0] != 0) ? 1 : 0;
}

__device__ __forceinline__ int load_idx(const void* ei, long long pos, int is32) {
    if (is32) return ((const int*)ei)[pos];
    return (int)((const long long*)ei)[pos];
}

// ---- 1) init: deg=1, column sums = 0 ----
__global__ void k_init(int n) {
    int i = blockIdx.x * blockDim.x + threadIdx.x;
    if (i < n) g_deg[i] = 1.0f;
    if (i < DIMK) { g_sum[i] = 0.0f; g_sumsq[i] = 0.0f; }
}

// ---- 2) degree: atomicAdd 1 per edge at dst ----
__global__ void k_deg(const void* __restrict__ ei, int E) {
    int e = blockIdx.x * blockDim.x + threadIdx.x;
    if (e >= E) return;
    int is32 = g_is32;
    int dst = load_idx(ei, (long long)E + e, is32);
    atomicAdd(&g_deg[dst], 1.0f);
}

// ---- 3) GEMM h = x@W, dinv = rsqrt(deg), acc = h * dinv^2 (self-loop) ----
// blockDim = (64, 8); each block handles 32 rows (4 per y-thread).
__global__ void k_gemm(const float* __restrict__ x, const float* __restrict__ W, int n) {
    __shared__ float Wsh[DIMK][DIMK + 1];
    __shared__ float xsh[32][DIMK + 1];
    int tx = threadIdx.x;            // 0..63 -> output col
    int ty = threadIdx.y;            // 0..7
    int tid = ty * 64 + tx;          // 0..511
    int row0 = blockIdx.x * 32;

    #pragma unroll
    for (int i = tid; i < DIMK * DIMK; i += 512)
        Wsh[i >> 6][i & 63] = W[i];
    for (int i = tid; i < 32 * DIMK; i += 512) {
        int r = row0 + (i >> 6);
        xsh[i >> 6][i & 63] = (r < n) ? x[(size_t)r * DIMK + (i & 63)] : 0.0f;
    }
    __syncthreads();

    #pragma unroll
    for (int rr = 0; rr < 4; rr++) {
        int lr = ty + rr * 8;
        int r = row0 + lr;
        if (r >= n) continue;
        float acc = 0.0f;
        #pragma unroll
        for (int k = 0; k < DIMK; k++)
            acc = fmaf(xsh[lr][k], Wsh[k][tx], acc);
        float dv = rsqrtf(g_deg[r]);
        if (tx == 0) g_dinv[r] = dv;
        size_t o = (size_t)r * DIMK + tx;
        g_h[o]   = acc;
        g_acc[o] = acc * dv * dv;
    }
}

// ---- 4) edge scatter: acc[dst] += dinv[src]*dinv[dst] * h[src] ----
// one thread per (edge, float4 group): E*16 threads, 4 scalar REDs each.
__global__ void k_scatter(const void* __restrict__ ei, int E) {
    long long gid = (long long)blockIdx.x * blockDim.x + threadIdx.x;
    if (gid >= (long long)E * 16) return;
    int e = (int)(gid >> 4);
    int g = (int)(gid & 15);
    int is32 = g_is32;
    int src = load_idx(ei, e, is32);
    int dst = load_idx(ei, (long long)E + e, is32);
    float norm = g_dinv[src] * g_dinv[dst];
    const float4 hv = *reinterpret_cast<const float4*>(&g_h[(size_t)src * DIMK + g * 4]);
    float* addr = &g_acc[(size_t)dst * DIMK + g * 4];
    atomicAdd(addr + 0, hv.x * norm);
    atomicAdd(addr + 1, hv.y * norm);
    atomicAdd(addr + 2, hv.z * norm);
    atomicAdd(addr + 3, hv.w * norm);
}

// ---- 5) BN column stats: per-block partial sums -> atomicAdd ----
// blockDim = 256: col = tid&63, row-group = tid>>6 (4 rows in flight).
__global__ void k_stats(int n) {
    int tid = threadIdx.x;
    int col = tid & 63;
    int rg  = tid >> 6;
    float s = 0.0f, s2 = 0.0f;
    for (int r = blockIdx.x * 4 + rg; r < n; r += gridDim.x * 4) {
        float v = g_acc[(size_t)r * DIMK + col];
        s += v; s2 += v * v;
    }
    __shared__ float sh[4][DIMK], sh2[4][DIMK];
    sh[rg][col] = s; sh2[rg][col] = s2;
    __syncthreads();
    if (rg == 0) {
        float ts  = sh[0][col] + sh[1][col] + sh[2][col] + sh[3][col];
        float ts2 = sh2[0][col] + sh2[1][col] + sh2[2][col] + sh2[3][col];
        atomicAdd(&g_sum[col], ts);
        atomicAdd(&g_sumsq[col], ts2);
    }
}

// ---- 6) finalize: BN (b cancels) -> ReLU -> L2 row-normalize -> out ----
// one warp per row; each lane handles cols (lane, lane+32).
__global__ void k_final(const float* __restrict__ gamma, const float* __restrict__ beta,
                        float* __restrict__ out, int n) {
    int warp = (blockIdx.x * blockDim.x + threadIdx.x) >> 5;
    int lane = threadIdx.x & 31;
    if (warp >= n) return;
    const float invN = 1.0f / (float)n;

    int c0 = lane, c1 = lane + 32;
    float m0 = g_sum[c0] * invN, m1 = g_sum[c1] * invN;
    float v0 = g_sumsq[c0] * invN - m0 * m0;
    float v1 = g_sumsq[c1] * invN - m1 * m1;
    float sc0 = rsqrtf(v0 + BN_EPS) * gamma[c0];
    float sc1 = rsqrtf(v1 + BN_EPS) * gamma[c1];

    size_t base = (size_t)warp * DIMK;
    float a0 = g_acc[base + c0];
    float a1 = g_acc[base + c1];
    float y0 = fmaf(a0 - m0, sc0, beta[c0]);
    float y1 = fmaf(a1 - m1, sc1, beta[c1]);
    y0 = fmaxf(y0, 0.0f);
    y1 = fmaxf(y1, 0.0f);

    float ss = y0 * y0 + y1 * y1;
    #pragma unroll
    for (int o = 16; o > 0; o >>= 1)
        ss += __shfl_xor_sync(0xffffffffu, ss, o);
    float nrm = sqrtf(ss);
    float inv = 1.0f / fmaxf(nrm, L2_EPS);
    out[base + c0] = y0 * inv;
    out[base + c1] = y1 * inv;
}

extern "C" void kernel_launch(void* const* d_in, const int* in_sizes, int n_in,
                              void* d_out, int out_size) {
    const float* x     = (const float*)d_in[0];
    const void*  ei    = d_in[1];                 // int32 or int64, probed at runtime
    const float* W     = (const float*)d_in[2];
    // const float* b  = (const float*)d_in[3];   // cancels exactly in BN
    const float* gamma = (const float*)d_in[4];
    const float* beta  = (const float*)d_in[5];
    float* out = (float*)d_out;

    int n = in_sizes[0] / DIMK;       // 50000
    int E = in_sizes[1] / 2;          // 800000

    k_probe<<<1, 256>>>((const unsigned int*)ei);
    k_init<<<(n + 255) / 256, 256>>>(n);
    k_deg<<<(E + 255) / 256, 256>>>(ei, E);
    {
        dim3 blk(64, 8);
        int grid = (n + 31) / 32;
        k_gemm<<<grid, blk>>>(x, W, n);
    }
    {
        long long total = (long long)E * 16;
        int grid = (int)((total + 255) / 256);
        k_scatter<<<grid, 256>>>(ei, E);
    }
    k_stats<<<256, 256>>>(n);
    {
        int rows_per_block = 256 / 32;  // 8 warps = 8 rows
        int grid = (n + rows_per_block - 1) / rows_per_block;
        k_final<<<grid, 256>>>(gamma, beta, out, n);
    }
}

// round 4
// speedup vs baseline: 1.9486x; 1.9486x over previous
#include <cuda_runtime.h>
#include <cuda_bf16.h>
#include <stdint.h>

#define NN 50000
#define EE 800000
#define DIMK 64
#define BN_EPS 1e-5f
#define L2_EPS 1e-12f

// ---- scratch (device globals; no allocation allowed) ----
__device__ __align__(16) float g_h[NN * DIMK];     // h = x @ W
__device__ __align__(16) float g_acc[NN * DIMK];   // accumulator (self-loop + edges)
__device__ float g_deg[NN];
__device__ float g_dinv[NN];
__device__ float g_sum[DIMK];
__device__ float g_sumsq[DIMK];
__device__ int   g_is32;                           // 1 if edge_index is int32
__device__ int   g_esrc[EE];
__device__ int   g_edst[EE];
__device__ float g_enorm[EE];

// ---- 0) probe edge_index dtype: int64 high words are all 0 for values in [0,N) ----
__global__ void k_probe(const unsigned int* __restrict__ ei32) {
    int tid = threadIdx.x;
    unsigned int acc = 0;
    for (int i = tid; i < 2048; i += 256)
        acc |= ei32[2 * i + 1];
    __shared__ unsigned int sh[256];
    sh[tid] = acc;
    __syncthreads();
    for (int s = 128; s > 0; s >>= 1) {
        if (tid < s) sh[tid] |= sh[tid + s];
        __syncthreads();
    }
    if (tid == 0) g_is32 = (sh[0] != 0) ? 1 : 0;
}

__device__ __forceinline__ int load_idx(const void* ei, long long pos, int is32) {
    if (is32) return ((const int*)ei)[pos];
    return (int)((const long long*)ei)[pos];
}

// ---- 1) init: deg=1, column sums = 0 ----
__global__ void k_init(int n) {
    int i = blockIdx.x * blockDim.x + threadIdx.x;
    if (i < n) g_deg[i] = 1.0f;
    if (i < DIMK) { g_sum[i] = 0.0f; g_sumsq[i] = 0.0f; }
}

// ---- 2) degree: atomicAdd 1 per edge at dst ----
__global__ void k_deg(const void* __restrict__ ei, int E) {
    int e = blockIdx.x * blockDim.x + threadIdx.x;
    if (e >= E) return;
    int is32 = g_is32;
    int dst = load_idx(ei, (long long)E + e, is32);
    atomicAdd(&g_deg[dst], 1.0f);
}

// ---- 2b) dinv = rsqrt(deg) ----
__global__ void k_dinv(int n) {
    int i = blockIdx.x * blockDim.x + threadIdx.x;
    if (i < n) g_dinv[i] = rsqrtf(g_deg[i]);
}

// ---- 2c) edge prep: int32 src/dst + per-edge norm (read int64 indices once) ----
__global__ void k_prep(const void* __restrict__ ei, int E) {
    int e = blockIdx.x * blockDim.x + threadIdx.x;
    if (e >= E) return;
    int is32 = g_is32;
    int src = load_idx(ei, e, is32);
    int dst = load_idx(ei, (long long)E + e, is32);
    g_esrc[e] = src;
    g_edst[e] = dst;
    g_enorm[e] = g_dinv[src] * g_dinv[dst];
}

// ---- 3) GEMM h = x@W (register-tiled 4x4), acc = h * dinv^2 (self-loop) ----
// block 256 threads, 64-row x 64-col tile; thread computes 4 rows x 4 cols.
__global__ void k_gemm(const float* __restrict__ x, const float* __restrict__ W, int n) {
    __shared__ float Wsh[DIMK][68];
    __shared__ float xsh[DIMK][68];
    int tid = threadIdx.x;                 // 0..255
    int row0 = blockIdx.x * 64;

    // load W (4096 floats) and x tile as float4
    for (int i = tid; i < 1024; i += 256) {
        int r  = i >> 4;
        int c4 = (i & 15) << 2;
        float4 v = ((const float4*)W)[i];
        *(float4*)&Wsh[r][c4] = v;
    }
    for (int i = tid; i < 1024; i += 256) {
        int r  = i >> 4;
        int c4 = (i & 15) << 2;
        int gr = row0 + r;
        float4 v = (gr < n) ? ((const float4*)x)[(size_t)gr * 16 + (i & 15)]
                            : make_float4(0.f, 0.f, 0.f, 0.f);
        *(float4*)&xsh[r][c4] = v;
    }
    __syncthreads();

    int tr = tid >> 4;            // 0..15 (row within group)
    int tc = (tid & 15) << 2;     // col base
    float acc[4][4] = {};
    #pragma unroll
    for (int k = 0; k < DIMK; k++) {
        float4 wv = *(const float4*)&Wsh[k][tc];
        float xv[4];
        #pragma unroll
        for (int i = 0; i < 4; i++) xv[i] = xsh[i * 16 + tr][k];
        #pragma unroll
        for (int i = 0; i < 4; i++) {
            acc[i][0] = fmaf(xv[i], wv.x, acc[i][0]);
            acc[i][1] = fmaf(xv[i], wv.y, acc[i][1]);
            acc[i][2] = fmaf(xv[i], wv.z, acc[i][2]);
            acc[i][3] = fmaf(xv[i], wv.w, acc[i][3]);
        }
    }
    #pragma unroll
    for (int i = 0; i < 4; i++) {
        int r = row0 + i * 16 + tr;
        if (r >= n) continue;
        float dv = g_dinv[r];
        float s = dv * dv;
        size_t o = (size_t)r * DIMK + tc;
        float4 hv = make_float4(acc[i][0], acc[i][1], acc[i][2], acc[i][3]);
        *(float4*)&g_h[o] = hv;
        float4 av = make_float4(hv.x * s, hv.y * s, hv.z * s, hv.w * s);
        *(float4*)&g_acc[o] = av;
    }
}

// ---- 4) edge scatter: acc[dst] += norm * h[src], 16B vector reductions ----
// one thread per (edge, float4 group): E*16 threads, 1 red.v4 each.
__global__ void k_scatter(int E) {
    long long gid = (long long)blockIdx.x * blockDim.x + threadIdx.x;
    if (gid >= (long long)E * 16) return;
    int e = (int)(gid >> 4);
    int g = (int)(gid & 15);
    int src = g_esrc[e];
    int dst = g_edst[e];
    float norm = g_enorm[e];
    const float4 hv = *reinterpret_cast<const float4*>(&g_h[(size_t)src * DIMK + g * 4]);
    float vx = hv.x * norm, vy = hv.y * norm, vz = hv.z * norm, vw = hv.w * norm;
    float* addr = &g_acc[(size_t)dst * DIMK + g * 4];
    asm volatile("red.global.add.v4.f32 [%0], {%1, %2, %3, %4};"
                 :: "l"(addr), "f"(vx), "f"(vy), "f"(vz), "f"(vw) : "memory");
}

// ---- 5) BN column stats: per-block partial sums -> atomicAdd ----
__global__ void k_stats(int n) {
    int tid = threadIdx.x;
    int col = tid & 63;
    int rg  = tid >> 6;
    float s = 0.0f, s2 = 0.0f;
    for (int r = blockIdx.x * 4 + rg; r < n; r += gridDim.x * 4) {
        float v = g_acc[(size_t)r * DIMK + col];
        s += v; s2 += v * v;
    }
    __shared__ float sh[4][DIMK], sh2[4][DIMK];
    sh[rg][col] = s; sh2[rg][col] = s2;
    __syncthreads();
    if (rg == 0) {
        float ts  = sh[0][col] + sh[1][col] + sh[2][col] + sh[3][col];
        float ts2 = sh2[0][col] + sh2[1][col] + sh2[2][col] + sh2[3][col];
        atomicAdd(&g_sum[col], ts);
        atomicAdd(&g_sumsq[col], ts2);
    }
}

// ---- 6) finalize: BN (b cancels) -> ReLU -> L2 row-normalize -> out ----
__global__ void k_final(const float* __restrict__ gamma, const float* __restrict__ beta,
                        float* __restrict__ out, int n) {
    int warp = (blockIdx.x * blockDim.x + threadIdx.x) >> 5;
    int lane = threadIdx.x & 31;
    if (warp >= n) return;
    const float invN = 1.0f / (float)n;

    int c0 = lane, c1 = lane + 32;
    float m0 = g_sum[c0] * invN, m1 = g_sum[c1] * invN;
    float v0 = g_sumsq[c0] * invN - m0 * m0;
    float v1 = g_sumsq[c1] * invN - m1 * m1;
    float sc0 = rsqrtf(v0 + BN_EPS) * gamma[c0];
    float sc1 = rsqrtf(v1 + BN_EPS) * gamma[c1];

    size_t base = (size_t)warp * DIMK;
    float a0 = g_acc[base + c0];
    float a1 = g_acc[base + c1];
    float y0 = fmaf(a0 - m0, sc0, beta[c0]);
    float y1 = fmaf(a1 - m1, sc1, beta[c1]);
    y0 = fmaxf(y0, 0.0f);
    y1 = fmaxf(y1, 0.0f);

    float ss = y0 * y0 + y1 * y1;
    #pragma unroll
    for (int o = 16; o > 0; o >>= 1)
        ss += __shfl_xor_sync(0xffffffffu, ss, o);
    float nrm = sqrtf(ss);
    float inv = 1.0f / fmaxf(nrm, L2_EPS);
    out[base + c0] = y0 * inv;
    out[base + c1] = y1 * inv;
}

extern "C" void kernel_launch(void* const* d_in, const int* in_sizes, int n_in,
                              void* d_out, int out_size) {
    const float* x     = (const float*)d_in[0];
    const void*  ei    = d_in[1];                 // int32 or int64, probed at runtime
    const float* W     = (const float*)d_in[2];
    // const float* b  = (const float*)d_in[3];   // cancels exactly in BN
    const float* gamma = (const float*)d_in[4];
    const float* beta  = (const float*)d_in[5];
    float* out = (float*)d_out;

    int n = in_sizes[0] / DIMK;       // 50000
    int E = in_sizes[1] / 2;          // 800000

    k_probe<<<1, 256>>>((const unsigned int*)ei);
    k_init<<<(n + 255) / 256, 256>>>(n);
    k_deg<<<(E + 255) / 256, 256>>>(ei, E);
    k_dinv<<<(n + 255) / 256, 256>>>(n);
    k_prep<<<(E + 255) / 256, 256>>>(ei, E);
    k_gemm<<<(n + 63) / 64, 256>>>(x, W, n);
    {
        long long total = (long long)E * 16;
        int grid = (int)((total + 255) / 256);
        k_scatter<<<grid, 256>>>(E);
    }
    k_stats<<<256, 256>>>(n);
    {
        int rows_per_block = 256 / 32;  // 8 warps = 8 rows
        int grid = (n + rows_per_block - 1) / rows_per_block;
        k_final<<<grid, 256>>>(gamma, beta, out, n);
    }
}